// round 16
// baseline (speedup 1.0000x reference)
#include <cuda_runtime.h>
#include <cuda_fp16.h>
#include <cstdint>

#define BB 2
#define NN 4096
#define HH 256
#define NHEADS 4
#define DH 64
#define MTOT (BB*NN)                 // 8192 rows
#define PLANE ((size_t)MTOT * HH)    // 2M elements

// ---------------------------------------------------------------------------
// Scratch (__device__ globals — no cudaMalloc allowed)
// ---------------------------------------------------------------------------
__device__ float g_Q [(size_t)MTOT * HH];
__device__ float g_K [(size_t)MTOT * HH];
__device__ float g_V [(size_t)MTOT * HH];
__device__ float g_AV[(size_t)MTOT * HH];
__device__ __half g_Qh[PLANE];           // fp16 Q (scores operand)
__device__ __half g_Kh[PLANE];           // fp16 K
__device__ __half g_Vf[2 * PLANE];       // fp16 V hi | lo (pv operand)
__device__ __half g_E [134217728ULL];    // 256 MB: E = exp(s - M_i), fp16
__device__ float g_il[8 * NN];           // 1/l per (bh,i)  (written by pv)
__device__ float g_M [8 * NN];           // row upper bound M_i
__device__ float g_kmax[8];              // max |k| per (b,h)
__device__ uint32_t g_adjbits[(size_t)NN * (NN / 32)];  // 2 MB packed mask

#define NEG_INF  __int_as_float(0xff800000)

// ---------------------------------------------------------------------------
// helpers
// ---------------------------------------------------------------------------
__device__ __forceinline__ uint32_t smem_u32(const void* p) {
    return (uint32_t)__cvta_generic_to_shared(p);
}
__device__ __forceinline__ void split_f16(float x, __half& h, __half& l) {
    h = __float2half_rn(x);
    l = __float2half_rn(x - __half2float(h));
}
__device__ __forceinline__ void ldsm_x4(uint32_t addr, uint32_t& r0, uint32_t& r1,
                                        uint32_t& r2, uint32_t& r3) {
    asm volatile("ldmatrix.sync.aligned.m8n8.x4.shared.b16 {%0,%1,%2,%3}, [%4];"
                 : "=r"(r0), "=r"(r1), "=r"(r2), "=r"(r3) : "r"(addr));
}
__device__ __forceinline__ void ldsm_x4_t(uint32_t addr, uint32_t& r0, uint32_t& r1,
                                          uint32_t& r2, uint32_t& r3) {
    asm volatile("ldmatrix.sync.aligned.m8n8.x4.trans.shared.b16 {%0,%1,%2,%3}, [%4];"
                 : "=r"(r0), "=r"(r1), "=r"(r2), "=r"(r3) : "r"(addr));
}
__device__ __forceinline__ void mma_f16(float* d, const uint32_t* a, const uint32_t* b) {
    asm volatile(
        "mma.sync.aligned.m16n8k16.row.col.f32.f16.f16.f32 "
        "{%0,%1,%2,%3}, {%4,%5,%6,%7}, {%8,%9}, {%0,%1,%2,%3};"
        : "+f"(d[0]), "+f"(d[1]), "+f"(d[2]), "+f"(d[3])
        : "r"(a[0]), "r"(a[1]), "r"(a[2]), "r"(a[3]), "r"(b[0]), "r"(b[1]));
}

// ---------------------------------------------------------------------------
// Pack adjacency into bitmask.
// ---------------------------------------------------------------------------
__global__ __launch_bounds__(256) void adj_pack(const int* __restrict__ adj)
{
    const int idx = blockIdx.x * 256 + threadIdx.x;
    const int row = idx >> 7, wc = idx & 127;
    const int* src = adj + (size_t)row * NN + wc * 32;
    uint32_t bits = 0;
    #pragma unroll
    for (int k = 0; k < 8; k++) {
        int4 v = *(const int4*)&src[k * 4];
        bits |= (v.x ? 1u : 0u) << (k * 4 + 0);
        bits |= (v.y ? 1u : 0u) << (k * 4 + 1);
        bits |= (v.z ? 1u : 0u) << (k * 4 + 2);
        bits |= (v.w ? 1u : 0u) << (k * 4 + 3);
    }
    g_adjbits[idx] = bits;
}

// ---------------------------------------------------------------------------
// Convert: Q,K fp32 -> fp16; V fp32 -> fp16 hi/lo. grid (2048, 3).
// ---------------------------------------------------------------------------
__global__ __launch_bounds__(256) void convert_qkv()
{
    const size_t idx = (size_t)blockIdx.x * 256 + threadIdx.x;   // float4 index
    if (blockIdx.y == 0) {
        float4 v = ((const float4*)g_Q)[idx];
        __half hv[4] = { __float2half_rn(v.x), __float2half_rn(v.y),
                         __float2half_rn(v.z), __float2half_rn(v.w) };
        ((uint2*)g_Qh)[idx] = *(uint2*)hv;
    } else if (blockIdx.y == 1) {
        float4 v = ((const float4*)g_K)[idx];
        __half hv[4] = { __float2half_rn(v.x), __float2half_rn(v.y),
                         __float2half_rn(v.z), __float2half_rn(v.w) };
        ((uint2*)g_Kh)[idx] = *(uint2*)hv;
    } else {
        float4 v = ((const float4*)g_V)[idx];
        __half hi[4], lo[4];
        split_f16(v.x, hi[0], lo[0]);
        split_f16(v.y, hi[1], lo[1]);
        split_f16(v.z, hi[2], lo[2]);
        split_f16(v.w, hi[3], lo[3]);
        ((uint2*)g_Vf)[idx]           = *(uint2*)hi;
        ((uint2*)(g_Vf + PLANE))[idx] = *(uint2*)lo;
    }
}

// ---------------------------------------------------------------------------
// K norms: max |k_j| per (b,h) via int atomicMax (non-negative floats).
// ---------------------------------------------------------------------------
__global__ __launch_bounds__(256) void knorm_kernel()
{
    const int idx = blockIdx.x * 256 + threadIdx.x;   // 32768
    const int i = idx & 4095, bh = idx >> 12;
    const int b = bh >> 2, h = bh & 3;
    const float* k = g_K + (size_t)(b * NN + i) * HH + h * DH;
    float s = 0.f;
    #pragma unroll
    for (int d = 0; d < 16; d++) {
        float4 v = *(const float4*)&k[d * 4];
        s += v.x * v.x + v.y * v.y + v.z * v.z + v.w * v.w;
    }
    atomicMax((int*)&g_kmax[bh], __float_as_int(sqrtf(s)));
}

// ---------------------------------------------------------------------------
// Row bound: M[bh,i] = |q_i| * kmax[bh] / 8 + max(cb, cb+cw)
// ---------------------------------------------------------------------------
__global__ __launch_bounds__(256) void qbound_kernel(
    const float* __restrict__ cw, const float* __restrict__ cb)
{
    const int idx = blockIdx.x * 256 + threadIdx.x;
    const int i = idx & 4095, bh = idx >> 12;
    const int b = bh >> 2, h = bh & 3;
    const float* q = g_Q + (size_t)(b * NN + i) * HH + h * DH;
    float s = 0.f;
    #pragma unroll
    for (int d = 0; d < 16; d++) {
        float4 v = *(const float4*)&q[d * 4];
        s += v.x * v.x + v.y * v.y + v.z * v.z + v.w * v.w;
    }
    const float bmax = fmaxf(cb[h], cb[h] + cw[h]);
    g_M[(size_t)bh * NN + i] = sqrtf(s) * g_kmax[bh] * 0.125f + bmax;
}

// ---------------------------------------------------------------------------
// GEMM core (fp16 hi/lo 3-pass). Tile 128m x 64n, k-chunks of 64.
// ---------------------------------------------------------------------------
#define LDG_ 136

__device__ __forceinline__ void gemm_body(
    const float* __restrict__ X, const float* __restrict__ W,
    const float* __restrict__ bias, float* __restrict__ Y,
    int m0, int n0, __half* Xs, __half* Ws)
{
    const int tid  = threadIdx.x;
    const int lane = tid & 31, warp = tid >> 5;
    const int wm = warp >> 2, wn = warp & 3;

    float acc[4][2][4] = {};
    const uint32_t xbase = smem_u32(Xs);
    const uint32_t wbase = smem_u32(Ws);

    for (int kc0 = 0; kc0 < HH; kc0 += 64) {
        __syncthreads();
        #pragma unroll
        for (int it = 0; it < 8; it++) {
            int f  = tid + it * 256;
            int r  = f >> 4;
            int dq = f & 15;
            float4 v = *(const float4*)&X[(size_t)(m0 + r) * HH + kc0 + dq * 4];
            __half hi[4], lo[4];
            split_f16(v.x, hi[0], lo[0]);
            split_f16(v.y, hi[1], lo[1]);
            split_f16(v.z, hi[2], lo[2]);
            split_f16(v.w, hi[3], lo[3]);
            *(uint2*)&Xs[r * LDG_ + dq * 4]      = *(uint2*)hi;
            *(uint2*)&Xs[r * LDG_ + 64 + dq * 4] = *(uint2*)lo;
        }
        #pragma unroll
        for (int it = 0; it < 4; it++) {
            int f  = tid + it * 256;
            int r  = f >> 4;
            int dq = f & 15;
            float4 v = *(const float4*)&W[(size_t)(n0 + r) * HH + kc0 + dq * 4];
            __half hi[4], lo[4];
            split_f16(v.x, hi[0], lo[0]);
            split_f16(v.y, hi[1], lo[1]);
            split_f16(v.z, hi[2], lo[2]);
            split_f16(v.w, hi[3], lo[3]);
            *(uint2*)&Ws[r * LDG_ + dq * 4]      = *(uint2*)hi;
            *(uint2*)&Ws[r * LDG_ + 64 + dq * 4] = *(uint2*)lo;
        }
        __syncthreads();

        #pragma unroll
        for (int pass = 0; pass < 3; pass++) {
            const int aOff = (pass == 1) ? 64 : 0;
            const int bOff = (pass == 2) ? 64 : 0;
            #pragma unroll
            for (int ks = 0; ks < 4; ks++) {
                const int kc = ks * 16;
                uint32_t a[4][4];
                #pragma unroll
                for (int mt = 0; mt < 4; mt++) {
                    int r = wm * 64 + mt * 16 + (lane & 15);
                    int c = aOff + kc + ((lane >> 4) << 3);
                    ldsm_x4(xbase + (uint32_t)(r * LDG_ + c) * 2,
                            a[mt][0], a[mt][1], a[mt][2], a[mt][3]);
                }
                uint32_t bf[2][2];
                {
                    int r = wn * 16 + ((lane >> 4) << 3) + (lane & 7);
                    int c = bOff + kc + (lane & 8);
                    uint32_t r0, r1, r2, r3;
                    ldsm_x4(wbase + (uint32_t)(r * LDG_ + c) * 2, r0, r1, r2, r3);
                    bf[0][0] = r0; bf[0][1] = r1;
                    bf[1][0] = r2; bf[1][1] = r3;
                }
                #pragma unroll
                for (int mt = 0; mt < 4; mt++)
                    #pragma unroll
                    for (int nt = 0; nt < 2; nt++)
                        mma_f16(acc[mt][nt], a[mt], bf[nt]);
            }
        }
    }

    const int g  = lane >> 2;
    const int t2 = (lane & 3) * 2;
    float2 bv[2];
    #pragma unroll
    for (int nt = 0; nt < 2; nt++)
        bv[nt] = *(const float2*)&bias[n0 + wn * 16 + nt * 8 + t2];

    #pragma unroll
    for (int mt = 0; mt < 4; mt++) {
        const int r0 = m0 + wm * 64 + mt * 16 + g;
        const int r1 = r0 + 8;
        #pragma unroll
        for (int nt = 0; nt < 2; nt++) {
            const int col = n0 + wn * 16 + nt * 8 + t2;
            float* ac = acc[mt][nt];
            *(float2*)&Y[(size_t)r0 * HH + col] = make_float2(ac[0] + bv[nt].x, ac[1] + bv[nt].y);
            *(float2*)&Y[(size_t)r1 * HH + col] = make_float2(ac[2] + bv[nt].x, ac[3] + bv[nt].y);
        }
    }
}

// fused QKV: grid (64, 4, 3); z selects projection
__global__ __launch_bounds__(256, 2) void gemm_qkv(
    const float* __restrict__ X,
    const float* __restrict__ Wq, const float* __restrict__ bq, float* __restrict__ Yq,
    const float* __restrict__ Wk, const float* __restrict__ bk, float* __restrict__ Yk,
    const float* __restrict__ Wv, const float* __restrict__ bv, float* __restrict__ Yv)
{
    extern __shared__ __half smg[];
    const float* W = (blockIdx.z == 0) ? Wq : (blockIdx.z == 1) ? Wk : Wv;
    const float* bb = (blockIdx.z == 0) ? bq : (blockIdx.z == 1) ? bk : bv;
    float* Y = (blockIdx.z == 0) ? Yq : (blockIdx.z == 1) ? Yk : Yv;
    gemm_body(X, W, bb, Y, blockIdx.x * 128, blockIdx.y * 64, smg, smg + 128 * LDG_);
}

__global__ __launch_bounds__(256, 2) void gemm_mma(
    const float* __restrict__ X, const float* __restrict__ W,
    const float* __restrict__ bias, float* __restrict__ Y)
{
    extern __shared__ __half smg[];
    gemm_body(X, W, bias, Y, blockIdx.x * 128, blockIdx.y * 64, smg, smg + 128 * LDG_);
}

// ---------------------------------------------------------------------------
// Scores -> E (single-pass fp16 mma): copy fills; epilogue
// E = bit ? exp(s - M_i) : 0 (fp16, smem-staged coalesced store).
// grid: x=bh(8), y=jt(32), z=it(32); 256 threads
// ---------------------------------------------------------------------------
#define LDS_ 72
#define STG  136

__global__ __launch_bounds__(256) void scores_e(
    const float* __restrict__ tau,
    const float* __restrict__ cw, const float* __restrict__ cb)
{
    extern __shared__ __half sm[];
    __half* Qs = sm;                 // [128][LDS_]
    __half* Ks = sm + 128 * LDS_;    // [128][LDS_]
    __half* stage = sm;              // [128][STG] (reuses Q/K post-mma)

    const int tid  = threadIdx.x;
    const int lane = tid & 31, warp = tid >> 5;
    const int wm = warp >> 2, wn = warp & 3;
    const int bh = blockIdx.x;
    const int b = bh >> 2, h = bh & 3;
    const int j0 = blockIdx.y * 128, i0 = blockIdx.z * 128;

    const __half* Qg = g_Qh + (size_t)(b * NN + i0) * HH + h * DH;
    const __half* Kg = g_Kh + (size_t)(b * NN + j0) * HH + h * DH;

    #pragma unroll
    for (int it = 0; it < 8; it++) {
        int f   = tid + it * 256;
        int mat = f >> 10;
        int r   = (f >> 3) & 127;
        int c8  = f & 7;
        const __half* src = (mat ? Kg : Qg) + (size_t)r * HH + c8 * 8;
        *(uint4*)&((mat ? Ks : Qs)[r * LDS_ + c8 * 8]) = *(const uint4*)src;
    }
    __syncthreads();

    float acc[4][4][4] = {};
    const uint32_t qbase = smem_u32(Qs);
    const uint32_t kbase = smem_u32(Ks);

    #pragma unroll
    for (int ks = 0; ks < 4; ks++) {
        const int kc = ks * 16;
        uint32_t a[4][4];
        #pragma unroll
        for (int mt = 0; mt < 4; mt++) {
            int r = wm * 64 + mt * 16 + (lane & 15);
            int c = kc + ((lane >> 4) << 3);
            ldsm_x4(qbase + (uint32_t)(r * LDS_ + c) * 2,
                    a[mt][0], a[mt][1], a[mt][2], a[mt][3]);
        }
        uint32_t bf[4][2];
        #pragma unroll
        for (int hf = 0; hf < 2; hf++) {
            int r = wn * 32 + hf * 16 + ((lane >> 4) << 3) + (lane & 7);
            int c = kc + (lane & 8);
            uint32_t r0, r1, r2, r3;
            ldsm_x4(kbase + (uint32_t)(r * LDS_ + c) * 2, r0, r1, r2, r3);
            bf[hf * 2 + 0][0] = r0; bf[hf * 2 + 0][1] = r1;
            bf[hf * 2 + 1][0] = r2; bf[hf * 2 + 1][1] = r3;
        }
        #pragma unroll
        for (int mt = 0; mt < 4; mt++)
            #pragma unroll
            for (int nt = 0; nt < 4; nt++)
                mma_f16(acc[mt][nt], a[mt], bf[nt]);
    }

    // epilogue: scale, bias, bit mask, exp(s - M) -> acc in place
    const float cwh = cw[h], cbh = cb[h];
    const float* taub = tau + (size_t)b * NN;
    const int g  = lane >> 2;
    const int t2 = (lane & 3) * 2;
    const int wordIdx = (j0 >> 5) + wn;

    float2 tj[4];
    #pragma unroll
    for (int nt = 0; nt < 4; nt++)
        tj[nt] = *(const float2*)&taub[j0 + wn * 32 + nt * 8 + t2];

    #pragma unroll
    for (int mt = 0; mt < 4; mt++) {
        const int r0 = i0 + wm * 64 + mt * 16 + g;
        const int r1 = r0 + 8;
        const float ti0 = taub[r0], ti1 = taub[r1];
        const float M0 = g_M[(size_t)bh * NN + r0];
        const float M1 = g_M[(size_t)bh * NN + r1];
        const uint32_t w0 = g_adjbits[(size_t)r0 * 128 + wordIdx];
        const uint32_t w1 = g_adjbits[(size_t)r1 * 128 + wordIdx];
        #pragma unroll
        for (int nt = 0; nt < 4; nt++) {
            const int bit = nt * 8 + t2;
            float* ac = acc[mt][nt];
            ac[0] = (w0 >> bit)       & 1 ? __expf(fmaf(ac[0], 0.125f, fmaf(ti0 * tj[nt].x, cwh, cbh)) - M0) : 0.f;
            ac[1] = (w0 >> (bit + 1)) & 1 ? __expf(fmaf(ac[1], 0.125f, fmaf(ti0 * tj[nt].y, cwh, cbh)) - M0) : 0.f;
            ac[2] = (w1 >> bit)       & 1 ? __expf(fmaf(ac[2], 0.125f, fmaf(ti1 * tj[nt].x, cwh, cbh)) - M1) : 0.f;
            ac[3] = (w1 >> (bit + 1)) & 1 ? __expf(fmaf(ac[3], 0.125f, fmaf(ti1 * tj[nt].y, cwh, cbh)) - M1) : 0.f;
        }
    }

    __syncthreads();

    #pragma unroll
    for (int mt = 0; mt < 4; mt++) {
        const int rl0 = wm * 64 + mt * 16 + g;
        const int rl1 = rl0 + 8;
        #pragma unroll
        for (int nt = 0; nt < 4; nt++) {
            const int cl = wn * 32 + nt * 8 + t2;
            float* ac = acc[mt][nt];
            *(__half2*)&stage[rl0 * STG + cl] = __floats2half2_rn(ac[0], ac[1]);
            *(__half2*)&stage[rl1 * STG + cl] = __floats2half2_rn(ac[2], ac[3]);
        }
    }
    __syncthreads();

    #pragma unroll
    for (int it = 0; it < 8; it++) {
        int f = tid + it * 256;
        int r = f >> 4;
        int c16 = f & 15;
        uint4 v = *(const uint4*)&stage[r * STG + c16 * 8];
        *(uint4*)&g_E[((size_t)bh * NN + i0 + r) * NN + j0 + c16 * 8] = v;
    }
}

// ---------------------------------------------------------------------------
// PV: AVu = sum_j E * V (E fills are pure copies; per-thread fp32 partial
// row-sums accumulated during fill -> l per row -> epilogue scales by 1/l,
// writes g_il for the am kernel). tile 128(i) x 64(d). grid: x=it(32), y=bh(8)
// ---------------------------------------------------------------------------
#define LDE 72
#define LDV 72

__global__ __launch_bounds__(256) void pv_mma()
{
    extern __shared__ __half smh[];
    __half* Ps = smh;                          // [128 i][LDE]
    __half* Vs = smh + 128 * LDE;              // [128 j(hi|lo)][LDV]
    float*  ls = (float*)(Vs + 128 * LDV);     // [128] row sums

    const int tid  = threadIdx.x;
    const int lane = tid & 31, warp = tid >> 5;
    const int wm = warp >> 1, wn = warp & 1;
    const int bh = blockIdx.y;
    const int b = bh >> 2, h = bh & 3;
    const int i0 = blockIdx.x * 128;

    float acc[2][4][4] = {};
    float ps[4] = {};                           // partial sums, 4 fixed rows/thread
    const uint32_t pbase = smem_u32(Ps);
    const uint32_t vbase = smem_u32(Vs);

    const __half* Eb = g_E + ((size_t)bh * NN + i0) * NN;
    const size_t voff = (size_t)(b * NN) * HH + h * DH;

    for (int jt = 0; jt < NN; jt += 64) {
        __syncthreads();
        // E tile: pure copy + partial sums
        #pragma unroll
        for (int it = 0; it < 4; it++) {
            int f = tid + it * 256;
            int r = f >> 3;
            int c = f & 7;
            uint4 u = *(const uint4*)(Eb + (size_t)r * NN + jt + c * 8);
            *(uint4*)(Ps + r * LDE + c * 8) = u;
            const __half2* hh = (const __half2*)&u;
            float s = 0.f;
            #pragma unroll
            for (int t = 0; t < 4; t++) {
                float2 fv = __half22float2(hh[t]);
                s += fv.x + fv.y;
            }
            ps[it] += s;
        }
        // V tile: copy from fp16 hi/lo planes
        #pragma unroll
        for (int it = 0; it < 4; it++) {
            int f  = tid + it * 256;
            int p  = f >> 9;
            int jr = (f >> 3) & 63;
            int c  = f & 7;
            *(uint4*)(Vs + (jr + p * 64) * LDV + c * 8) =
                *(const uint4*)(g_Vf + (size_t)p * PLANE + voff + (size_t)(jt + jr) * HH + c * 8);
        }
        __syncthreads();

        #pragma unroll
        for (int ks = 0; ks < 4; ks++) {
            const int kc = ks * 16;
            uint32_t a[2][4];
            #pragma unroll
            for (int mt = 0; mt < 2; mt++) {
                int r = wm * 32 + mt * 16 + (lane & 15);
                int c = kc + ((lane >> 4) << 3);
                ldsm_x4(pbase + (uint32_t)(r * LDE + c) * 2,
                        a[mt][0], a[mt][1], a[mt][2], a[mt][3]);
            }
            #pragma unroll
            for (int pass = 0; pass < 2; pass++) {
                const int bOff = pass * 64;
                uint32_t bf[4][2];
                #pragma unroll
                for (int hf = 0; hf < 2; hf++) {
                    int r = bOff + kc + (lane & 7) + ((lane & 8) ? 8 : 0);
                    int c = wn * 32 + hf * 16 + ((lane >> 4) << 3);
                    uint32_t r0, r1, r2, r3;
                    ldsm_x4_t(vbase + (uint32_t)(r * LDV + c) * 2, r0, r1, r2, r3);
                    bf[hf * 2 + 0][0] = r0; bf[hf * 2 + 0][1] = r1;
                    bf[hf * 2 + 1][0] = r2; bf[hf * 2 + 1][1] = r3;
                }
                #pragma unroll
                for (int mt = 0; mt < 2; mt++)
                    #pragma unroll
                    for (int nt = 0; nt < 4; nt++)
                        mma_f16(acc[mt][nt], a[mt], bf[nt]);
            }
        }
    }

    // reduce partial sums over the 8 threads sharing each row (same warp)
    #pragma unroll
    for (int it = 0; it < 4; it++) {
        #pragma unroll
        for (int o = 1; o < 8; o <<= 1)
            ps[it] += __shfl_xor_sync(0xffffffffu, ps[it], o);
    }
    __syncthreads();
    if ((tid & 7) == 0) {
        #pragma unroll
        for (int it = 0; it < 4; it++) {
            int r = (tid >> 3) + it * 32;
            ls[r] = ps[it];
            g_il[(size_t)bh * NN + i0 + r] = 1.0f / ps[it];
        }
    }
    __syncthreads();

    const int g  = lane >> 2;
    const int t2 = (lane & 3) * 2;
    #pragma unroll
    for (int mt = 0; mt < 2; mt++) {
        const int rl0 = wm * 32 + mt * 16 + g;
        const int rl1 = rl0 + 8;
        const int r0 = i0 + rl0;
        const int r1 = i0 + rl1;
        const float il0 = 1.0f / ls[rl0];
        const float il1 = 1.0f / ls[rl1];
        #pragma unroll
        for (int nt = 0; nt < 4; nt++) {
            const int d = wn * 32 + nt * 8 + t2;
            float* ac = acc[mt][nt];
            *(float2*)&g_AV[(size_t)(b * NN + r0) * HH + h * DH + d] =
                make_float2(ac[0] * il0, ac[1] * il0);
            *(float2*)&g_AV[(size_t)(b * NN + r1) * HH + h * DH + d] =
                make_float2(ac[2] * il1, ac[3] * il1);
        }
    }
}

// ---------------------------------------------------------------------------
// attn mean: am[b,i,j] = 0.25 * sum_h E[bh,i,j] * il[bh,i]
// Pure streaming; grid 8192 CTAs (b,i); 256 threads; 16 cols/thread.
// ---------------------------------------------------------------------------
__global__ __launch_bounds__(256) void am_kernel(float* __restrict__ out_am)
{
    const int bi = blockIdx.x;
    const int b = bi >> 12, i = bi & 4095;
    const int tid = threadIdx.x;

    float acc[16] = {};
    #pragma unroll
    for (int h = 0; h < 4; h++) {
        const int bh = b * 4 + h;
        const float ilh = 0.25f * g_il[(size_t)bh * NN + i];
        const __half* row = g_E + ((size_t)bh * NN + i) * NN + tid * 16;
        uint4 u0 = *(const uint4*)row;
        uint4 u1 = *(const uint4*)(row + 8);
        const __half2* h0 = (const __half2*)&u0;
        const __half2* h1 = (const __half2*)&u1;
        #pragma unroll
        for (int t = 0; t < 4; t++) {
            float2 f0 = __half22float2(h0[t]);
            float2 f1 = __half22float2(h1[t]);
            acc[t * 2 + 0] = fmaf(f0.x, ilh, acc[t * 2 + 0]);
            acc[t * 2 + 1] = fmaf(f0.y, ilh, acc[t * 2 + 1]);
            acc[8 + t * 2 + 0] = fmaf(f1.x, ilh, acc[8 + t * 2 + 0]);
            acc[8 + t * 2 + 1] = fmaf(f1.y, ilh, acc[8 + t * 2 + 1]);
        }
    }
    float* am = out_am + ((size_t)(b * NN) + i) * NN + tid * 16;
    #pragma unroll
    for (int r = 0; r < 4; r++)
        *(float4*)&am[r * 4] = make_float4(acc[r*4+0], acc[r*4+1], acc[r*4+2], acc[r*4+3]);
}

// ---------------------------------------------------------------------------
// Launch
// inputs: 0:h 1:tau 2:adj_mask 3:Wq 4:bq 5:Wk 6:bk 7:Wv 8:bv 9:cw 10:cb 11:Wo 12:bo
// ---------------------------------------------------------------------------
extern "C" void kernel_launch(void* const* d_in, const int* in_sizes, int n_in,
                              void* d_out, int out_size)
{
    const float* h_in = (const float*)d_in[0];
    const float* tau  = (const float*)d_in[1];
    const int*   adj  = (const int*)  d_in[2];
    const float* Wq   = (const float*)d_in[3];
    const float* bq   = (const float*)d_in[4];
    const float* Wk   = (const float*)d_in[5];
    const float* bk   = (const float*)d_in[6];
    const float* Wv   = (const float*)d_in[7];
    const float* bv   = (const float*)d_in[8];
    const float* cw   = (const float*)d_in[9];
    const float* cb   = (const float*)d_in[10];
    const float* Wo   = (const float*)d_in[11];
    const float* bo   = (const float*)d_in[12];

    float* out_h  = (float*)d_out;
    float* out_am = out_h + (size_t)MTOT * HH;

    void *pQ, *pK, *pV, *pAV, *pKmax;
    cudaGetSymbolAddress(&pQ,  g_Q);
    cudaGetSymbolAddress(&pK,  g_K);
    cudaGetSymbolAddress(&pV,  g_V);
    cudaGetSymbolAddress(&pAV, g_AV);
    cudaGetSymbolAddress(&pKmax, g_kmax);

    const int smem_gemm   = (128 + 64) * LDG_ * 2;               // 52224 B
    const int smem_scores = 2 * 128 * LDS_ * 2;                  // 36864 B
    const int smem_pv     = (128 * LDE + 128 * LDV) * 2 + 512;   // 37376 B
    cudaFuncSetAttribute(gemm_qkv, cudaFuncAttributeMaxDynamicSharedMemorySize, smem_gemm);
    cudaFuncSetAttribute(gemm_mma, cudaFuncAttributeMaxDynamicSharedMemorySize, smem_gemm);
    cudaFuncSetAttribute(scores_e, cudaFuncAttributeMaxDynamicSharedMemorySize, smem_scores);
    cudaFuncSetAttribute(pv_mma,   cudaFuncAttributeMaxDynamicSharedMemorySize, smem_pv);

    adj_pack<<<2048, 256>>>(adj);

    gemm_qkv<<<dim3(MTOT / 128, HH / 64, 3), 256, smem_gemm>>>(
        h_in, Wq, bq, (float*)pQ, Wk, bk, (float*)pK, Wv, bv, (float*)pV);

    convert_qkv<<<dim3(PLANE / 4 / 256, 3), 256>>>();

    cudaMemsetAsync(pKmax, 0, 8 * sizeof(float));
    knorm_kernel<<<128, 256>>>();
    qbound_kernel<<<128, 256>>>(cw, cb);

    scores_e<<<dim3(BB * NHEADS, NN / 128, NN / 128), 256, smem_scores>>>(tau, cw, cb);

    pv_mma<<<dim3(NN / 128, BB * NHEADS), 256, smem_pv>>>();

    am_kernel<<<BB * NN, 256>>>(out_am);

    gemm_mma<<<dim3(MTOT / 128, HH / 64), 256, smem_gemm>>>((const float*)pAV, Wo, bo, out_h);
}

// round 17
// speedup vs baseline: 1.0969x; 1.0969x over previous
#include <cuda_runtime.h>
#include <cuda_fp16.h>
#include <cstdint>

#define BB 2
#define NN 4096
#define HH 256
#define NHEADS 4
#define DH 64
#define MTOT (BB*NN)                 // 8192 rows
#define PLANE ((size_t)MTOT * HH)    // 2M elements

// ---------------------------------------------------------------------------
// Scratch (__device__ globals — no cudaMalloc allowed)
// ---------------------------------------------------------------------------
__device__ float g_Q [(size_t)MTOT * HH];
__device__ float g_K [(size_t)MTOT * HH];
__device__ float g_V [(size_t)MTOT * HH];
__device__ float g_AV[(size_t)MTOT * HH];
__device__ __half g_Qh[PLANE];           // fp16 Q (scores operand)
__device__ __half g_Kh[PLANE];           // fp16 K
__device__ __half g_Vh[PLANE];           // fp16 V (pv operand, single plane)
__device__ __half g_S [134217728ULL];    // 256 MB scores (fp16)
__device__ float g_m [8 * NN];           // row max per (bh,i)
__device__ float g_il[8 * NN];           // 1/l per (bh,i)
__device__ uint32_t g_adjbits[(size_t)NN * (NN / 32)];  // 2 MB packed mask

#define NEG_INF  __int_as_float(0xff800000)
#define MASK_F16 (-65504.0f)

// ---------------------------------------------------------------------------
// helpers
// ---------------------------------------------------------------------------
__device__ __forceinline__ uint32_t smem_u32(const void* p) {
    return (uint32_t)__cvta_generic_to_shared(p);
}
__device__ __forceinline__ void split_f16(float x, __half& h, __half& l) {
    h = __float2half_rn(x);
    l = __float2half_rn(x - __half2float(h));
}
__device__ __forceinline__ void ldsm_x4(uint32_t addr, uint32_t& r0, uint32_t& r1,
                                        uint32_t& r2, uint32_t& r3) {
    asm volatile("ldmatrix.sync.aligned.m8n8.x4.shared.b16 {%0,%1,%2,%3}, [%4];"
                 : "=r"(r0), "=r"(r1), "=r"(r2), "=r"(r3) : "r"(addr));
}
__device__ __forceinline__ void ldsm_x4_t(uint32_t addr, uint32_t& r0, uint32_t& r1,
                                          uint32_t& r2, uint32_t& r3) {
    asm volatile("ldmatrix.sync.aligned.m8n8.x4.trans.shared.b16 {%0,%1,%2,%3}, [%4];"
                 : "=r"(r0), "=r"(r1), "=r"(r2), "=r"(r3) : "r"(addr));
}
__device__ __forceinline__ void mma_f16(float* d, const uint32_t* a, const uint32_t* b) {
    asm volatile(
        "mma.sync.aligned.m16n8k16.row.col.f32.f16.f16.f32 "
        "{%0,%1,%2,%3}, {%4,%5,%6,%7}, {%8,%9}, {%0,%1,%2,%3};"
        : "+f"(d[0]), "+f"(d[1]), "+f"(d[2]), "+f"(d[3])
        : "r"(a[0]), "r"(a[1]), "r"(a[2]), "r"(a[3]), "r"(b[0]), "r"(b[1]));
}

// ---------------------------------------------------------------------------
// Pack adjacency into bitmask.
// ---------------------------------------------------------------------------
__global__ __launch_bounds__(256) void adj_pack(const int* __restrict__ adj)
{
    const int idx = blockIdx.x * 256 + threadIdx.x;
    const int row = idx >> 7, wc = idx & 127;
    const int* src = adj + (size_t)row * NN + wc * 32;
    uint32_t bits = 0;
    #pragma unroll
    for (int k = 0; k < 8; k++) {
        int4 v = *(const int4*)&src[k * 4];
        bits |= (v.x ? 1u : 0u) << (k * 4 + 0);
        bits |= (v.y ? 1u : 0u) << (k * 4 + 1);
        bits |= (v.z ? 1u : 0u) << (k * 4 + 2);
        bits |= (v.w ? 1u : 0u) << (k * 4 + 3);
    }
    g_adjbits[idx] = bits;
}

// ---------------------------------------------------------------------------
// Convert: Q,K,V fp32 -> fp16. grid (2048, 3).
// ---------------------------------------------------------------------------
__global__ __launch_bounds__(256) void convert_qkv()
{
    const size_t idx = (size_t)blockIdx.x * 256 + threadIdx.x;   // float4 index
    const float* src = (blockIdx.y == 0) ? g_Q : (blockIdx.y == 1) ? g_K : g_V;
    __half* dst = (blockIdx.y == 0) ? g_Qh : (blockIdx.y == 1) ? g_Kh : g_Vh;
    float4 v = ((const float4*)src)[idx];
    __half hv[4] = { __float2half_rn(v.x), __float2half_rn(v.y),
                     __float2half_rn(v.z), __float2half_rn(v.w) };
    ((uint2*)dst)[idx] = *(uint2*)hv;
}

// ---------------------------------------------------------------------------
// GEMM core (fp16 hi/lo 3-pass). Tile 128m x 64n, k-chunks of 64.
// ---------------------------------------------------------------------------
#define LDG_ 136

__device__ __forceinline__ void gemm_body(
    const float* __restrict__ X, const float* __restrict__ W,
    const float* __restrict__ bias, float* __restrict__ Y,
    int m0, int n0, __half* Xs, __half* Ws)
{
    const int tid  = threadIdx.x;
    const int lane = tid & 31, warp = tid >> 5;
    const int wm = warp >> 2, wn = warp & 3;

    float acc[4][2][4] = {};
    const uint32_t xbase = smem_u32(Xs);
    const uint32_t wbase = smem_u32(Ws);

    for (int kc0 = 0; kc0 < HH; kc0 += 64) {
        __syncthreads();
        #pragma unroll
        for (int it = 0; it < 8; it++) {
            int f  = tid + it * 256;
            int r  = f >> 4;
            int dq = f & 15;
            float4 v = *(const float4*)&X[(size_t)(m0 + r) * HH + kc0 + dq * 4];
            __half hi[4], lo[4];
            split_f16(v.x, hi[0], lo[0]);
            split_f16(v.y, hi[1], lo[1]);
            split_f16(v.z, hi[2], lo[2]);
            split_f16(v.w, hi[3], lo[3]);
            *(uint2*)&Xs[r * LDG_ + dq * 4]      = *(uint2*)hi;
            *(uint2*)&Xs[r * LDG_ + 64 + dq * 4] = *(uint2*)lo;
        }
        #pragma unroll
        for (int it = 0; it < 4; it++) {
            int f  = tid + it * 256;
            int r  = f >> 4;
            int dq = f & 15;
            float4 v = *(const float4*)&W[(size_t)(n0 + r) * HH + kc0 + dq * 4];
            __half hi[4], lo[4];
            split_f16(v.x, hi[0], lo[0]);
            split_f16(v.y, hi[1], lo[1]);
            split_f16(v.z, hi[2], lo[2]);
            split_f16(v.w, hi[3], lo[3]);
            *(uint2*)&Ws[r * LDG_ + dq * 4]      = *(uint2*)hi;
            *(uint2*)&Ws[r * LDG_ + 64 + dq * 4] = *(uint2*)lo;
        }
        __syncthreads();

        #pragma unroll
        for (int pass = 0; pass < 3; pass++) {
            const int aOff = (pass == 1) ? 64 : 0;
            const int bOff = (pass == 2) ? 64 : 0;
            #pragma unroll
            for (int ks = 0; ks < 4; ks++) {
                const int kc = ks * 16;
                uint32_t a[4][4];
                #pragma unroll
                for (int mt = 0; mt < 4; mt++) {
                    int r = wm * 64 + mt * 16 + (lane & 15);
                    int c = aOff + kc + ((lane >> 4) << 3);
                    ldsm_x4(xbase + (uint32_t)(r * LDG_ + c) * 2,
                            a[mt][0], a[mt][1], a[mt][2], a[mt][3]);
                }
                uint32_t bf[2][2];
                {
                    int r = wn * 16 + ((lane >> 4) << 3) + (lane & 7);
                    int c = bOff + kc + (lane & 8);
                    uint32_t r0, r1, r2, r3;
                    ldsm_x4(wbase + (uint32_t)(r * LDG_ + c) * 2, r0, r1, r2, r3);
                    bf[0][0] = r0; bf[0][1] = r1;
                    bf[1][0] = r2; bf[1][1] = r3;
                }
                #pragma unroll
                for (int mt = 0; mt < 4; mt++)
                    #pragma unroll
                    for (int nt = 0; nt < 2; nt++)
                        mma_f16(acc[mt][nt], a[mt], bf[nt]);
            }
        }
    }

    const int g  = lane >> 2;
    const int t2 = (lane & 3) * 2;
    float2 bv[2];
    #pragma unroll
    for (int nt = 0; nt < 2; nt++)
        bv[nt] = *(const float2*)&bias[n0 + wn * 16 + nt * 8 + t2];

    #pragma unroll
    for (int mt = 0; mt < 4; mt++) {
        const int r0 = m0 + wm * 64 + mt * 16 + g;
        const int r1 = r0 + 8;
        #pragma unroll
        for (int nt = 0; nt < 2; nt++) {
            const int col = n0 + wn * 16 + nt * 8 + t2;
            float* ac = acc[mt][nt];
            *(float2*)&Y[(size_t)r0 * HH + col] = make_float2(ac[0] + bv[nt].x, ac[1] + bv[nt].y);
            *(float2*)&Y[(size_t)r1 * HH + col] = make_float2(ac[2] + bv[nt].x, ac[3] + bv[nt].y);
        }
    }
}

// fused QKV: grid (64, 4, 3); z selects projection
__global__ __launch_bounds__(256, 2) void gemm_qkv(
    const float* __restrict__ X,
    const float* __restrict__ Wq, const float* __restrict__ bq, float* __restrict__ Yq,
    const float* __restrict__ Wk, const float* __restrict__ bk, float* __restrict__ Yk,
    const float* __restrict__ Wv, const float* __restrict__ bv, float* __restrict__ Yv)
{
    extern __shared__ __half smg[];
    const float* W = (blockIdx.z == 0) ? Wq : (blockIdx.z == 1) ? Wk : Wv;
    const float* bb = (blockIdx.z == 0) ? bq : (blockIdx.z == 1) ? bk : bv;
    float* Y = (blockIdx.z == 0) ? Yq : (blockIdx.z == 1) ? Yk : Yv;
    gemm_body(X, W, bb, Y, blockIdx.x * 128, blockIdx.y * 64, smg, smg + 128 * LDG_);
}

__global__ __launch_bounds__(256, 2) void gemm_mma(
    const float* __restrict__ X, const float* __restrict__ W,
    const float* __restrict__ bias, float* __restrict__ Y)
{
    extern __shared__ __half smg[];
    gemm_body(X, W, bias, Y, blockIdx.x * 128, blockIdx.y * 64, smg, smg + 128 * LDG_);
}

// ---------------------------------------------------------------------------
// Scores (single-pass fp16 mma): copy fills from g_Qh/g_Kh.
// S = (Q.K)/8 + tau_i*tau_j*cw[h] + cb[h]; mask via packed bits -> -65504.
// grid: x=bh(8), y=jt(32), z=it(32); 256 threads
// ---------------------------------------------------------------------------
#define LDS_ 72
#define STG  136

__global__ __launch_bounds__(256) void scores_f16(
    const float* __restrict__ tau,
    const float* __restrict__ cw, const float* __restrict__ cb)
{
    extern __shared__ __half sm[];
    __half* Qs = sm;                 // [128][LDS_]
    __half* Ks = sm + 128 * LDS_;    // [128][LDS_]
    __half* stage = sm;              // [128][STG] (reuses Q/K post-mma)

    const int tid  = threadIdx.x;
    const int lane = tid & 31, warp = tid >> 5;
    const int wm = warp >> 2, wn = warp & 3;
    const int bh = blockIdx.x;
    const int b = bh >> 2, h = bh & 3;
    const int j0 = blockIdx.y * 128, i0 = blockIdx.z * 128;

    const __half* Qg = g_Qh + (size_t)(b * NN + i0) * HH + h * DH;
    const __half* Kg = g_Kh + (size_t)(b * NN + j0) * HH + h * DH;

    // fill: 2048 uint4 chunks (copy)
    #pragma unroll
    for (int it = 0; it < 8; it++) {
        int f   = tid + it * 256;
        int mat = f >> 10;
        int r   = (f >> 3) & 127;
        int c8  = f & 7;
        const __half* src = (mat ? Kg : Qg) + (size_t)r * HH + c8 * 8;
        *(uint4*)&((mat ? Ks : Qs)[r * LDS_ + c8 * 8]) = *(const uint4*)src;
    }
    __syncthreads();

    float acc[4][4][4] = {};
    const uint32_t qbase = smem_u32(Qs);
    const uint32_t kbase = smem_u32(Ks);

    #pragma unroll
    for (int ks = 0; ks < 4; ks++) {
        const int kc = ks * 16;
        uint32_t a[4][4];
        #pragma unroll
        for (int mt = 0; mt < 4; mt++) {
            int r = wm * 64 + mt * 16 + (lane & 15);
            int c = kc + ((lane >> 4) << 3);
            ldsm_x4(qbase + (uint32_t)(r * LDS_ + c) * 2,
                    a[mt][0], a[mt][1], a[mt][2], a[mt][3]);
        }
        uint32_t bf[4][2];
        #pragma unroll
        for (int hf = 0; hf < 2; hf++) {
            int r = wn * 32 + hf * 16 + ((lane >> 4) << 3) + (lane & 7);
            int c = kc + (lane & 8);
            uint32_t r0, r1, r2, r3;
            ldsm_x4(kbase + (uint32_t)(r * LDS_ + c) * 2, r0, r1, r2, r3);
            bf[hf * 2 + 0][0] = r0; bf[hf * 2 + 0][1] = r1;
            bf[hf * 2 + 1][0] = r2; bf[hf * 2 + 1][1] = r3;
        }
        #pragma unroll
        for (int mt = 0; mt < 4; mt++)
            #pragma unroll
            for (int nt = 0; nt < 4; nt++)
                mma_f16(acc[mt][nt], a[mt], bf[nt]);
    }

    // epilogue: scale, credibility bias, packed-bit mask -> acc (in place)
    const float cwh = cw[h], cbh = cb[h];
    const float* taub = tau + (size_t)b * NN;
    const int g  = lane >> 2;
    const int t2 = (lane & 3) * 2;
    const int wordIdx = (j0 >> 5) + wn;

    float2 tj[4];
    #pragma unroll
    for (int nt = 0; nt < 4; nt++)
        tj[nt] = *(const float2*)&taub[j0 + wn * 32 + nt * 8 + t2];

    #pragma unroll
    for (int mt = 0; mt < 4; mt++) {
        const int r0 = i0 + wm * 64 + mt * 16 + g;
        const int r1 = r0 + 8;
        const float ti0 = taub[r0], ti1 = taub[r1];
        const uint32_t w0 = g_adjbits[(size_t)r0 * 128 + wordIdx];
        const uint32_t w1 = g_adjbits[(size_t)r1 * 128 + wordIdx];
        #pragma unroll
        for (int nt = 0; nt < 4; nt++) {
            const int bit = nt * 8 + t2;
            float* ac = acc[mt][nt];
            ac[0] = (w0 >> bit)       & 1 ? fmaf(ac[0], 0.125f, fmaf(ti0 * tj[nt].x, cwh, cbh)) : MASK_F16;
            ac[1] = (w0 >> (bit + 1)) & 1 ? fmaf(ac[1], 0.125f, fmaf(ti0 * tj[nt].y, cwh, cbh)) : MASK_F16;
            ac[2] = (w1 >> bit)       & 1 ? fmaf(ac[2], 0.125f, fmaf(ti1 * tj[nt].x, cwh, cbh)) : MASK_F16;
            ac[3] = (w1 >> (bit + 1)) & 1 ? fmaf(ac[3], 0.125f, fmaf(ti1 * tj[nt].y, cwh, cbh)) : MASK_F16;
        }
    }

    __syncthreads();

    #pragma unroll
    for (int mt = 0; mt < 4; mt++) {
        const int rl0 = wm * 64 + mt * 16 + g;
        const int rl1 = rl0 + 8;
        #pragma unroll
        for (int nt = 0; nt < 4; nt++) {
            const int cl = wn * 32 + nt * 8 + t2;
            float* ac = acc[mt][nt];
            *(__half2*)&stage[rl0 * STG + cl] = __floats2half2_rn(ac[0], ac[1]);
            *(__half2*)&stage[rl1 * STG + cl] = __floats2half2_rn(ac[2], ac[3]);
        }
    }
    __syncthreads();

    #pragma unroll
    for (int it = 0; it < 8; it++) {
        int f = tid + it * 256;
        int r = f >> 4;
        int c16 = f & 15;
        uint4 v = *(const uint4*)&stage[r * STG + c16 * 8];
        *(uint4*)&g_S[((size_t)bh * NN + i0 + r) * NN + j0 + c16 * 8] = v;
    }
}

// ---------------------------------------------------------------------------
// Softmax stats + head-mean: reads S fp16 (no write-back), computes m + 1/l,
// writes am from fp32 registers. One CTA per (b,i).
// ---------------------------------------------------------------------------
__device__ __forceinline__ float warpMax(float v) {
    #pragma unroll
    for (int o = 16; o > 0; o >>= 1) v = fmaxf(v, __shfl_xor_sync(0xffffffffu, v, o));
    return v;
}
__device__ __forceinline__ float warpSum(float v) {
    #pragma unroll
    for (int o = 16; o > 0; o >>= 1) v += __shfl_xor_sync(0xffffffffu, v, o);
    return v;
}

__global__ __launch_bounds__(256) void softmax_kernel(float* __restrict__ out_am)
{
    const int bi = blockIdx.x;
    const int b = bi >> 12, i = bi & 4095;
    const int tid = threadIdx.x;
    const int lane = tid & 31, wid = tid >> 5;
    __shared__ float red[8];

    float macc[16];
    #pragma unroll
    for (int r = 0; r < 16; r++) macc[r] = 0.f;

    for (int h = 0; h < NHEADS; h++) {
        const int bh = b * 4 + h;
        const __half* row = g_S + ((size_t)bh * NN + i) * NN;
        float p[16];
        #pragma unroll
        for (int r = 0; r < 4; r++) {
            uint2 u = *(const uint2*)&row[(tid + r * 256) * 4];
            const __half2* hh = (const __half2*)&u;
            float2 f0 = __half22float2(hh[0]);
            float2 f1 = __half22float2(hh[1]);
            p[r * 4 + 0] = f0.x; p[r * 4 + 1] = f0.y;
            p[r * 4 + 2] = f1.x; p[r * 4 + 3] = f1.y;
        }
        float m = p[0];
        #pragma unroll
        for (int r = 1; r < 16; r++) m = fmaxf(m, p[r]);
        m = warpMax(m);
        if (lane == 0) red[wid] = m;
        __syncthreads();
        if (wid == 0) {
            float x = (lane < 8) ? red[lane] : NEG_INF;
            x = warpMax(x);
            if (lane == 0) red[0] = x;
        }
        __syncthreads();
        m = red[0];
        __syncthreads();
        float s = 0.f;
        #pragma unroll
        for (int r = 0; r < 16; r++) { p[r] = __expf(p[r] - m); s += p[r]; }
        s = warpSum(s);
        if (lane == 0) red[wid] = s;
        __syncthreads();
        if (wid == 0) {
            float x = (lane < 8) ? red[lane] : 0.f;
            x = warpSum(x);
            if (lane == 0) red[0] = x;
        }
        __syncthreads();
        float inv = 1.0f / red[0];
        __syncthreads();

        if (tid == 0) {
            g_m [(size_t)bh * NN + i] = m;
            g_il[(size_t)bh * NN + i] = inv;
        }
        #pragma unroll
        for (int r = 0; r < 16; r++) macc[r] += p[r] * inv;
    }

    float* am = out_am + ((size_t)(b * NN) + i) * NN;
    #pragma unroll
    for (int r = 0; r < 4; r++) {
        float4 v = make_float4(macc[r*4+0] * 0.25f, macc[r*4+1] * 0.25f,
                               macc[r*4+2] * 0.25f, macc[r*4+3] * 0.25f);
        *(float4*)&am[(tid + r * 256) * 4] = v;
    }
}

// ---------------------------------------------------------------------------
// PV: exp(S - m) inline during fill; V single fp16 plane (1 B-pass).
// tile 128(i) x 64(d). grid: x=it(32), y=bh(8)
// ---------------------------------------------------------------------------
#define LDE 72
#define LDV 72

__global__ __launch_bounds__(256) void pv_mma()
{
    extern __shared__ __half smh[];
    __half* Ps = smh;                   // [128 i][LDE]
    __half* Vs = smh + 128 * LDE;       // [64 j][LDV]

    const int tid  = threadIdx.x;
    const int lane = tid & 31, warp = tid >> 5;
    const int wm = warp >> 1, wn = warp & 1;
    const int bh = blockIdx.y;
    const int b = bh >> 2, h = bh & 3;
    const int i0 = blockIdx.x * 128;

    float acc[2][4][4] = {};
    const uint32_t pbase = smem_u32(Ps);
    const uint32_t vbase = smem_u32(Vs);

    const __half* Sb = g_S + ((size_t)bh * NN + i0) * NN;
    const size_t voff = (size_t)(b * NN) * HH + h * DH;
    const float* mb = g_m + (size_t)bh * NN + i0;

    for (int jt = 0; jt < NN; jt += 64) {
        __syncthreads();
        // P tile: read S fp16, exp(s - m) inline -> fp16
        #pragma unroll
        for (int it = 0; it < 4; it++) {
            int f = tid + it * 256;
            int r = f >> 3;
            int c = f & 7;
            uint4 u = *(const uint4*)(Sb + (size_t)r * NN + jt + c * 8);
            const __half2* hh = (const __half2*)&u;
            const float m = mb[r];
            __half out[8];
            #pragma unroll
            for (int t = 0; t < 4; t++) {
                float2 fv = __half22float2(hh[t]);
                *(__half2*)&out[t * 2] =
                    __floats2half2_rn(__expf(fv.x - m), __expf(fv.y - m));
            }
            *(uint4*)(Ps + r * LDE + c * 8) = *(uint4*)out;
        }
        // V tile: 64 rows x 64 cols fp16 = 512 uint4 (pure copy)
        #pragma unroll
        for (int it = 0; it < 2; it++) {
            int f  = tid + it * 256;
            int jr = f >> 3;
            int c  = f & 7;
            *(uint4*)(Vs + jr * LDV + c * 8) =
                *(const uint4*)(g_Vh + voff + (size_t)(jt + jr) * HH + c * 8);
        }
        __syncthreads();

        #pragma unroll
        for (int ks = 0; ks < 4; ks++) {
            const int kc = ks * 16;
            uint32_t a[2][4];
            #pragma unroll
            for (int mt = 0; mt < 2; mt++) {
                int r = wm * 32 + mt * 16 + (lane & 15);
                int c = kc + ((lane >> 4) << 3);
                ldsm_x4(pbase + (uint32_t)(r * LDE + c) * 2,
                        a[mt][0], a[mt][1], a[mt][2], a[mt][3]);
            }
            uint32_t bf[4][2];
            #pragma unroll
            for (int hf = 0; hf < 2; hf++) {
                int r = kc + (lane & 7) + ((lane & 8) ? 8 : 0);
                int c = wn * 32 + hf * 16 + ((lane >> 4) << 3);
                uint32_t r0, r1, r2, r3;
                ldsm_x4_t(vbase + (uint32_t)(r * LDV + c) * 2, r0, r1, r2, r3);
                bf[hf * 2 + 0][0] = r0; bf[hf * 2 + 0][1] = r1;
                bf[hf * 2 + 1][0] = r2; bf[hf * 2 + 1][1] = r3;
            }
            #pragma unroll
            for (int mt = 0; mt < 2; mt++)
                #pragma unroll
                for (int nt = 0; nt < 4; nt++)
                    mma_f16(acc[mt][nt], a[mt], bf[nt]);
        }
    }

    const int g  = lane >> 2;
    const int t2 = (lane & 3) * 2;
    #pragma unroll
    for (int mt = 0; mt < 2; mt++) {
        const int r0 = i0 + wm * 32 + mt * 16 + g;
        const int r1 = r0 + 8;
        const float il0 = g_il[(size_t)bh * NN + r0];
        const float il1 = g_il[(size_t)bh * NN + r1];
        #pragma unroll
        for (int nt = 0; nt < 4; nt++) {
            const int d = wn * 32 + nt * 8 + t2;
            float* ac = acc[mt][nt];
            *(float2*)&g_AV[(size_t)(b * NN + r0) * HH + h * DH + d] =
                make_float2(ac[0] * il0, ac[1] * il0);
            *(float2*)&g_AV[(size_t)(b * NN + r1) * HH + h * DH + d] =
                make_float2(ac[2] * il1, ac[3] * il1);
        }
    }
}

// ---------------------------------------------------------------------------
// Launch
// inputs: 0:h 1:tau 2:adj_mask 3:Wq 4:bq 5:Wk 6:bk 7:Wv 8:bv 9:cw 10:cb 11:Wo 12:bo
// ---------------------------------------------------------------------------
extern "C" void kernel_launch(void* const* d_in, const int* in_sizes, int n_in,
                              void* d_out, int out_size)
{
    const float* h_in = (const float*)d_in[0];
    const float* tau  = (const float*)d_in[1];
    const int*   adj  = (const int*)  d_in[2];
    const float* Wq   = (const float*)d_in[3];
    const float* bq   = (const float*)d_in[4];
    const float* Wk   = (const float*)d_in[5];
    const float* bk   = (const float*)d_in[6];
    const float* Wv   = (const float*)d_in[7];
    const float* bv   = (const float*)d_in[8];
    const float* cw   = (const float*)d_in[9];
    const float* cb   = (const float*)d_in[10];
    const float* Wo   = (const float*)d_in[11];
    const float* bo   = (const float*)d_in[12];

    float* out_h  = (float*)d_out;
    float* out_am = out_h + (size_t)MTOT * HH;

    void *pQ, *pK, *pV, *pAV;
    cudaGetSymbolAddress(&pQ,  g_Q);
    cudaGetSymbolAddress(&pK,  g_K);
    cudaGetSymbolAddress(&pV,  g_V);
    cudaGetSymbolAddress(&pAV, g_AV);

    const int smem_gemm   = (128 + 64) * LDG_ * 2;         // 52224 B
    const int smem_scores = 2 * 128 * LDS_ * 2;            // 36864 B
    const int smem_pv     = (128 * LDE + 64 * LDV) * 2;    // 27648 B
    cudaFuncSetAttribute(gemm_qkv,   cudaFuncAttributeMaxDynamicSharedMemorySize, smem_gemm);
    cudaFuncSetAttribute(gemm_mma,   cudaFuncAttributeMaxDynamicSharedMemorySize, smem_gemm);
    cudaFuncSetAttribute(scores_f16, cudaFuncAttributeMaxDynamicSharedMemorySize, smem_scores);
    cudaFuncSetAttribute(pv_mma,     cudaFuncAttributeMaxDynamicSharedMemorySize, smem_pv);

    adj_pack<<<2048, 256>>>(adj);

    gemm_qkv<<<dim3(MTOT / 128, HH / 64, 3), 256, smem_gemm>>>(
        h_in, Wq, bq, (float*)pQ, Wk, bk, (float*)pK, Wv, bv, (float*)pV);

    convert_qkv<<<dim3(PLANE / 4 / 256, 3), 256>>>();

    scores_f16<<<dim3(BB * NHEADS, NN / 128, NN / 128), 256, smem_scores>>>(tau, cw, cb);

    softmax_kernel<<<BB * NN, 256>>>(out_am);

    pv_mma<<<dim3(NN / 128, BB * NHEADS), 256, smem_pv>>>();

    gemm_mma<<<dim3(MTOT / 128, HH / 64), 256, smem_gemm>>>((const float*)pAV, Wo, bo, out_h);
}